// round 8
// baseline (speedup 1.0000x reference)
#include <cuda_runtime.h>
#include <cstdint>

#define B_  2048
#define E_  32
#define N_  32
#define D_  64
#define BE_ (B_*E_)

__device__ __forceinline__ uint32_t smem_u32(const void* p) {
    return (uint32_t)__cvta_generic_to_shared(p);
}
__device__ __forceinline__ void cp_async16(uint32_t dst, const void* src) {
    asm volatile("cp.async.cg.shared.global [%0], [%1], 16;\n"
                 :: "r"(dst), "l"(src) : "memory");
}
#define CP_COMMIT() asm volatile("cp.async.commit_group;\n" ::: "memory")
#define CP_WAIT0()  asm volatile("cp.async.wait_group 0;\n" ::: "memory")

// One warp per (b,e) pair (R5 structure), plus a cp.async pipeline: the NEXT
// pair's rel tile (iters 0-7, 4KB) is staged into a warp-private smem buffer
// during the current pair's pass-2/epilogue, so the warp keeps loads in
// flight through the only previously memory-silent window. The compiler
// cannot sink LDGSTS (explicit commit/wait), unlike the failed R6 register
// pipeline. Lane l covers dims [4q..4q+3], q=l&15; load-iter i covers
// neighbor rows 2i,2i+1 (512B/warp).
__global__ __launch_bounds__(256, 3)
void sum_aggregator_kernel(const float* __restrict__ selfv,   // [B,E,D]
                           const float* __restrict__ nbv,     // [B,E,N,D]
                           const float* __restrict__ relv,    // [B,E,N,D]
                           const float* __restrict__ userv,   // [B,D]
                           const float* __restrict__ W,       // [D,D] row-major
                           const float* __restrict__ bl,      // [D]
                           float* __restrict__ out,           // [B,E,D]
                           int total_warps)
{
    __shared__ float4 Wa[16][32];          // Wa[c][l] = W[2l][4c..4c+3]
    __shared__ float4 Wb[16][32];          // Wb[c][l] = W[2l+1][4c..4c+3]
    __shared__ float4 relbuf[8][8][32];    // [warp][iter][lane] 32KB staging

    const int tid  = threadIdx.x;
    const int lane = tid & 31;
    const int wid  = tid >> 5;
    const int q    = lane & 15;

    for (int i = tid; i < 16 * 32; i += 256) {
        int c = i >> 5, l = i & 31;
        Wa[c][l] = *reinterpret_cast<const float4*>(W + (2*l  )*D_ + 4*c);
        Wb[c][l] = *reinterpret_cast<const float4*>(W + (2*l+1)*D_ + 4*c);
    }
    __syncthreads();

    const float2 bb = *reinterpret_cast<const float2*>(bl + 2*lane);
    const uint32_t mybuf = smem_u32(&relbuf[wid][0][lane]);   // +i*512B per iter

    int pair = blockIdx.x * 8 + wid;

    // ---- Prologue: stage first pair's rel iters 0-7 ----
    if (pair < BE_) {
        const float* relp = relv + (size_t)pair * (N_*D_);
        #pragma unroll
        for (int i = 0; i < 8; i++)
            cp_async16(mybuf + i*512, relp + i*128 + 4*lane);
    }
    CP_COMMIT();

    while (pair < BE_) {
        const int npair = pair + total_warps;
        const float* relp = relv + (size_t)pair * (N_*D_);
        const float* nbp  = nbv  + (size_t)pair * (N_*D_);
        const float4 u = *reinterpret_cast<const float4*>(
            userv + (size_t)(pair >> 5) * D_ + 4*q);

        // ---- Direct loads first (16 LDG.128 front-batched): rel iters 8-15
        // and nb iters 0-7. They fly while we wait + LDS the staged half. ----
        float4 r8[8];
        #pragma unroll
        for (int i = 0; i < 8; i++)
            r8[i] = *reinterpret_cast<const float4*>(relp + (8+i)*128 + 4*lane);
        float4 p0[8];
        #pragma unroll
        for (int i = 0; i < 8; i++)
            p0[i] = *reinterpret_cast<const float4*>(nbp + i*128 + 4*lane);

        // ---- Staged half: wait + LDS dots ----
        CP_WAIT0();
        float v[16];
        #pragma unroll
        for (int i = 0; i < 8; i++) {
            float4 r = relbuf[wid][i][lane];
            v[i] = u.x*r.x + u.y*r.y + u.z*r.z + u.w*r.w;
        }
        #pragma unroll
        for (int i = 0; i < 8; i++)
            v[8+i] = u.x*r8[i].x + u.y*r8[i].y + u.z*r8[i].z + u.w*r8[i].w;

        // ---- Reduce-scatter within 16-lane halves: lane owns score of
        // neighbor n(l) = 2*(l&15) + (l>>4). ----
        #pragma unroll
        for (int off = 8; off >= 1; off >>= 1) {
            const bool up = (lane & off) != 0;
            #pragma unroll
            for (int k = 0; k < off; k++) {
                float mine = up ? v[off + k] : v[k];
                float oth  = up ? v[k]       : v[off + k];
                v[k] = mine + __shfl_xor_sync(0xffffffffu, oth, off);
            }
        }
        float s = v[0] * (1.0f / (float)D_);

        // ---- Softmax (scores O(1): no max-subtraction needed) ----
        float e = __expf(s);
        float sum = e;
        #pragma unroll
        for (int off = 16; off >= 1; off >>= 1)
            sum += __shfl_xor_sync(0xffffffffu, sum, off);
        const float a = e / (sum * (float)N_);   // /N (mean) folded in

        // ---- Pipeline: stage NEXT pair's rel iters 0-7. The buffer's old
        // contents were consumed above; these LDGSTS stay in flight through
        // pass-2 + the entire epilogue. ----
        if (npair < BE_) {
            const float* relpn = relv + (size_t)npair * (N_*D_);
            #pragma unroll
            for (int i = 0; i < 8; i++)
                cp_async16(mybuf + i*512, relpn + i*128 + 4*lane);
        }
        CP_COMMIT();

        // ---- Pass 2a: consume prefetched nb half ----
        float4 acc = make_float4(0.f, 0.f, 0.f, 0.f);
        #pragma unroll
        for (int i = 0; i < 8; i++) {
            float an = __shfl_sync(0xffffffffu, a, i + (lane & 16));
            acc.x = fmaf(an, p0[i].x, acc.x);
            acc.y = fmaf(an, p0[i].y, acc.y);
            acc.z = fmaf(an, p0[i].z, acc.z);
            acc.w = fmaf(an, p0[i].w, acc.w);
        }
        // ---- Pass 2b: second nb half inline ----
        #pragma unroll
        for (int i = 8; i < 16; i++) {
            float4 x = *reinterpret_cast<const float4*>(nbp + i*128 + 4*lane);
            float an = __shfl_sync(0xffffffffu, a, i + (lane & 16));
            acc.x = fmaf(an, x.x, acc.x);
            acc.y = fmaf(an, x.y, acc.y);
            acc.z = fmaf(an, x.z, acc.z);
            acc.w = fmaf(an, x.w, acc.w);
        }
        // Fold even/odd halves.
        acc.x += __shfl_xor_sync(0xffffffffu, acc.x, 16);
        acc.y += __shfl_xor_sync(0xffffffffu, acc.y, 16);
        acc.z += __shfl_xor_sync(0xffffffffu, acc.z, 16);
        acc.w += __shfl_xor_sync(0xffffffffu, acc.w, 16);

        const float4 sv = *reinterpret_cast<const float4*>(
            selfv + (size_t)pair*D_ + 4*q);
        float4 o = make_float4(sv.x + acc.x, sv.y + acc.y,
                               sv.z + acc.z, sv.w + acc.w);

        // ---- Linear: y[j] = b[j] + sum_d o[d]*W[j][d], j = 2*lane, 2*lane+1 ----
        float y0 = bb.x, y1 = bb.y;
        #pragma unroll
        for (int c = 0; c < 16; c++) {
            float ox = __shfl_sync(0xffffffffu, o.x, c);
            float oy = __shfl_sync(0xffffffffu, o.y, c);
            float oz = __shfl_sync(0xffffffffu, o.z, c);
            float ow = __shfl_sync(0xffffffffu, o.w, c);
            float4 wa = Wa[c][lane];
            float4 wb = Wb[c][lane];
            y0 = fmaf(ox, wa.x, fmaf(oy, wa.y, fmaf(oz, wa.z, fmaf(ow, wa.w, y0))));
            y1 = fmaf(ox, wb.x, fmaf(oy, wb.y, fmaf(oz, wb.z, fmaf(ow, wb.w, y1))));
        }

        *reinterpret_cast<float2*>(out + (size_t)pair*D_ + 2*lane) =
            make_float2(fmaxf(y0, 0.f), fmaxf(y1, 0.f));

        pair = npair;
    }
}

extern "C" void kernel_launch(void* const* d_in, const int* in_sizes, int n_in,
                              void* d_out, int out_size)
{
    const float* selfv = (const float*)d_in[0];  // self_vectors      [B,E,D]
    const float* nbv   = (const float*)d_in[1];  // neighbor_vectors  [B,E,N,D]
    const float* relv  = (const float*)d_in[2];  // neighbor_relations[B,E,N,D]
    const float* userv = (const float*)d_in[3];  // user_embeddings   [B,D]
    // d_in[4] = masks (unused)
    const float* W     = (const float*)d_in[5];  // [D,D]
    const float* bl    = (const float*)d_in[6];  // [D]
    float* out = (float*)d_out;

    int dev = 0, sms = 152, occ = 0;
    cudaGetDevice(&dev);
    cudaDeviceGetAttribute(&sms, cudaDevAttrMultiProcessorCount, dev);
    cudaOccupancyMaxActiveBlocksPerMultiprocessor(&occ, sum_aggregator_kernel, 256, 0);
    if (occ < 1) occ = 1;
    if (occ > 3) occ = 3;    // 24 warps/SM measured best (R5)
    int blocks = occ * sms;
    int max_blocks = BE_ / 8;
    if (blocks > max_blocks) blocks = max_blocks;
    int total_warps = blocks * 8;

    sum_aggregator_kernel<<<blocks, 256>>>(selfv, nbv, relv, userv, W, bl, out,
                                           total_warps);
}

// round 9
// speedup vs baseline: 1.0201x; 1.0201x over previous
#include <cuda_runtime.h>

#define B_  2048
#define E_  32
#define N_  32
#define D_  64
#define BE_ (B_*E_)

// One warp per (b,e) pair (R5 structure — measured best). Lane l covers dims
// [4q..4q+3] with q = l&15; each LDG.128 fetches TWO neighbor rows (512B per
// warp). First half of the nb tile is prefetched before the softmax chain.
// Epilogue broadcast uses smem (1 STS + 16 broadcast LDS.128) instead of the
// 64-shfl chain, cutting the per-pair memory-silent window.
__global__ __launch_bounds__(256, 3)
void sum_aggregator_kernel(const float* __restrict__ selfv,   // [B,E,D]
                           const float* __restrict__ nbv,     // [B,E,N,D]
                           const float* __restrict__ relv,    // [B,E,N,D]
                           const float* __restrict__ userv,   // [B,D]
                           const float* __restrict__ W,       // [D,D] row-major
                           const float* __restrict__ bl,      // [D]
                           float* __restrict__ out,           // [B,E,D]
                           int total_warps)
{
    // Wa[c][l] = W[2l][4c..4c+3], Wb[c][l] = W[2l+1][4c..4c+3]
    __shared__ float4 Wa[16][32];
    __shared__ float4 Wb[16][32];
    __shared__ float4 osm[8][16];    // per-warp broadcast buffer for o

    const int tid  = threadIdx.x;
    const int lane = tid & 31;
    const int wid  = tid >> 5;
    const int q    = lane & 15;

    for (int i = tid; i < 16 * 32; i += 256) {
        int c = i >> 5, l = i & 31;
        Wa[c][l] = *reinterpret_cast<const float4*>(W + (2*l  )*D_ + 4*c);
        Wb[c][l] = *reinterpret_cast<const float4*>(W + (2*l+1)*D_ + 4*c);
    }
    __syncthreads();

    const float2 bb = *reinterpret_cast<const float2*>(bl + 2*lane);

    int gwarp = blockIdx.x * 8 + wid;
    for (int pair = gwarp; pair < BE_; pair += total_warps) {
        const int b = pair >> 5;  // / E_
        const float4 u = *reinterpret_cast<const float4*>(userv + (size_t)b*D_ + 4*q);

        const float* relp = relv + (size_t)pair * (N_*D_);
        const float* nbp  = nbv  + (size_t)pair * (N_*D_);

        // ---- Pass 1: partial scores (iter i covers neighbor rows 2i,2i+1) ----
        float v[16];
        #pragma unroll
        for (int i = 0; i < 16; i++) {
            float4 r = *reinterpret_cast<const float4*>(relp + i*128 + 4*lane);
            v[i] = u.x*r.x + u.y*r.y + u.z*r.z + u.w*r.w;
        }

        // ---- Prefetch first half of nb tile (independent of score chain) ----
        float4 p0[8];
        #pragma unroll
        for (int i = 0; i < 8; i++)
            p0[i] = *reinterpret_cast<const float4*>(nbp + i*128 + 4*lane);

        // ---- Reduce-scatter within 16-lane halves: lane owns the score of
        // neighbor n(l) = 2*(l&15) + (l>>4). ----
        #pragma unroll
        for (int off = 8; off >= 1; off >>= 1) {
            const bool up = (lane & off) != 0;
            #pragma unroll
            for (int k = 0; k < off; k++) {
                float mine = up ? v[off + k] : v[k];
                float oth  = up ? v[k]       : v[off + k];
                v[k] = mine + __shfl_xor_sync(0xffffffffu, oth, off);
            }
        }
        float s = v[0] * (1.0f / (float)D_);

        // ---- Softmax (scores O(1): no max-subtraction needed) ----
        float e = __expf(s);
        float sum = e;
        #pragma unroll
        for (int off = 16; off >= 1; off >>= 1)
            sum += __shfl_xor_sync(0xffffffffu, sum, off);
        const float a = e / (sum * (float)N_);   // /N (mean) folded in

        // ---- Pass 2a: consume prefetched half ----
        float4 acc = make_float4(0.f, 0.f, 0.f, 0.f);
        #pragma unroll
        for (int i = 0; i < 8; i++) {
            float an = __shfl_sync(0xffffffffu, a, i + (lane & 16));
            acc.x = fmaf(an, p0[i].x, acc.x);
            acc.y = fmaf(an, p0[i].y, acc.y);
            acc.z = fmaf(an, p0[i].z, acc.z);
            acc.w = fmaf(an, p0[i].w, acc.w);
        }
        // ---- Pass 2b: second half inline ----
        #pragma unroll
        for (int i = 8; i < 16; i++) {
            float4 x = *reinterpret_cast<const float4*>(nbp + i*128 + 4*lane);
            float an = __shfl_sync(0xffffffffu, a, i + (lane & 16));
            acc.x = fmaf(an, x.x, acc.x);
            acc.y = fmaf(an, x.y, acc.y);
            acc.z = fmaf(an, x.z, acc.z);
            acc.w = fmaf(an, x.w, acc.w);
        }
        // Fold even/odd halves: lanes 0-15 now hold the full agg for q=lane.
        acc.x += __shfl_xor_sync(0xffffffffu, acc.x, 16);
        acc.y += __shfl_xor_sync(0xffffffffu, acc.y, 16);
        acc.z += __shfl_xor_sync(0xffffffffu, acc.z, 16);
        acc.w += __shfl_xor_sync(0xffffffffu, acc.w, 16);

        const float4 sv = *reinterpret_cast<const float4*>(
            selfv + (size_t)pair*D_ + 4*q);
        float4 o = make_float4(sv.x + acc.x, sv.y + acc.y,
                               sv.z + acc.z, sv.w + acc.w);

        // ---- Broadcast o via smem: 1 STS.128 (lanes 0-15) + 16 LDS.128 ----
        if (lane < 16) osm[wid][lane] = o;
        __syncwarp();

        // ---- Linear: y[j] = b[j] + sum_d o[d]*W[j][d], j = 2*lane, 2*lane+1 ----
        float y0 = bb.x, y1 = bb.y;
        #pragma unroll
        for (int c = 0; c < 16; c++) {
            float4 oc = osm[wid][c];      // broadcast (same address, N=1)
            float4 wa = Wa[c][lane];
            float4 wb = Wb[c][lane];
            y0 = fmaf(oc.x, wa.x, fmaf(oc.y, wa.y, fmaf(oc.z, wa.z, fmaf(oc.w, wa.w, y0))));
            y1 = fmaf(oc.x, wb.x, fmaf(oc.y, wb.y, fmaf(oc.z, wb.z, fmaf(oc.w, wb.w, y1))));
        }
        __syncwarp();   // protect osm before next iteration overwrites it

        float2 res = make_float2(fmaxf(y0, 0.f), fmaxf(y1, 0.f));
        *reinterpret_cast<float2*>(out + (size_t)pair*D_ + 2*lane) = res;
    }
}

extern "C" void kernel_launch(void* const* d_in, const int* in_sizes, int n_in,
                              void* d_out, int out_size)
{
    const float* selfv = (const float*)d_in[0];  // self_vectors      [B,E,D]
    const float* nbv   = (const float*)d_in[1];  // neighbor_vectors  [B,E,N,D]
    const float* relv  = (const float*)d_in[2];  // neighbor_relations[B,E,N,D]
    const float* userv = (const float*)d_in[3];  // user_embeddings   [B,D]
    // d_in[4] = masks (unused)
    const float* W     = (const float*)d_in[5];  // [D,D]
    const float* bl    = (const float*)d_in[6];  // [D]
    float* out = (float*)d_out;

    int dev = 0, sms = 152, occ = 0;
    cudaGetDevice(&dev);
    cudaDeviceGetAttribute(&sms, cudaDevAttrMultiProcessorCount, dev);
    cudaOccupancyMaxActiveBlocksPerMultiprocessor(&occ, sum_aggregator_kernel, 256, 0);
    if (occ < 1) occ = 1;
    if (occ > 3) occ = 3;    // 24 warps/SM measured best (R5)
    int blocks = occ * sms;
    int max_blocks = BE_ / 8;
    if (blocks > max_blocks) blocks = max_blocks;
    int total_warps = blocks * 8;

    sum_aggregator_kernel<<<blocks, 256>>>(selfv, nbv, relv, userv, W, bl, out,
                                           total_warps);
}

// round 10
// speedup vs baseline: 1.0328x; 1.0125x over previous
#include <cuda_runtime.h>

#define B_  2048
#define E_  32
#define N_  32
#define D_  64
#define BE_ (B_*E_)

// R5 structure (measured best: 165.5us, DRAM 85.4%) + streaming cache hints.
// One warp per (b,e) pair. Lane l covers dims [4q..4q+3] with q = l&15;
// each LDG.128 fetches TWO neighbor rows (512B per warp). First half of the
// nb tile is prefetched before the softmax dependency chain. rel/nb tiles
// are single-use: __ldcs (evict-first) keeps them from thrashing L2 against
// the reused userv/W/selfv lines; __stcs on the output stream.
__global__ __launch_bounds__(256, 3)
void sum_aggregator_kernel(const float* __restrict__ selfv,   // [B,E,D]
                           const float* __restrict__ nbv,     // [B,E,N,D]
                           const float* __restrict__ relv,    // [B,E,N,D]
                           const float* __restrict__ userv,   // [B,D]
                           const float* __restrict__ W,       // [D,D] row-major
                           const float* __restrict__ bl,      // [D]
                           float* __restrict__ out,           // [B,E,D]
                           int total_warps)
{
    // Wa[c][l] = W[2l][4c..4c+3], Wb[c][l] = W[2l+1][4c..4c+3]
    __shared__ float4 Wa[16][32];
    __shared__ float4 Wb[16][32];

    const int tid  = threadIdx.x;
    const int lane = tid & 31;
    const int wid  = tid >> 5;
    const int q    = lane & 15;

    for (int i = tid; i < 16 * 32; i += 256) {
        int c = i >> 5, l = i & 31;
        Wa[c][l] = *reinterpret_cast<const float4*>(W + (2*l  )*D_ + 4*c);
        Wb[c][l] = *reinterpret_cast<const float4*>(W + (2*l+1)*D_ + 4*c);
    }
    __syncthreads();

    const float2 bb = *reinterpret_cast<const float2*>(bl + 2*lane);

    int gwarp = blockIdx.x * 8 + wid;
    for (int pair = gwarp; pair < BE_; pair += total_warps) {
        const int b = pair >> 5;  // / E_
        const float4 u = *reinterpret_cast<const float4*>(userv + (size_t)b*D_ + 4*q);

        const float* relp = relv + (size_t)pair * (N_*D_);
        const float* nbp  = nbv  + (size_t)pair * (N_*D_);

        // ---- Pass 1: partial scores (iter i covers neighbor rows 2i,2i+1) ----
        float v[16];
        #pragma unroll
        for (int i = 0; i < 16; i++) {
            float4 r = __ldcs(reinterpret_cast<const float4*>(relp + i*128 + 4*lane));
            v[i] = u.x*r.x + u.y*r.y + u.z*r.z + u.w*r.w;
        }

        // ---- Prefetch first half of nb tile (independent of score chain) ----
        float4 p0[8];
        #pragma unroll
        for (int i = 0; i < 8; i++)
            p0[i] = __ldcs(reinterpret_cast<const float4*>(nbp + i*128 + 4*lane));

        // ---- Reduce-scatter within 16-lane halves: lane owns the score of
        // neighbor n(l) = 2*(l&15) + (l>>4). ----
        #pragma unroll
        for (int off = 8; off >= 1; off >>= 1) {
            const bool up = (lane & off) != 0;
            #pragma unroll
            for (int k = 0; k < off; k++) {
                float mine = up ? v[off + k] : v[k];
                float oth  = up ? v[k]       : v[off + k];
                v[k] = mine + __shfl_xor_sync(0xffffffffu, oth, off);
            }
        }
        float s = v[0] * (1.0f / (float)D_);

        // ---- Softmax (scores O(1): no max-subtraction needed) ----
        float e = __expf(s);
        float sum = e;
        #pragma unroll
        for (int off = 16; off >= 1; off >>= 1)
            sum += __shfl_xor_sync(0xffffffffu, sum, off);
        const float a = e / (sum * (float)N_);   // /N (mean) folded in

        // ---- Pass 2a: consume prefetched half ----
        float4 acc = make_float4(0.f, 0.f, 0.f, 0.f);
        #pragma unroll
        for (int i = 0; i < 8; i++) {
            float an = __shfl_sync(0xffffffffu, a, i + (lane & 16));
            acc.x = fmaf(an, p0[i].x, acc.x);
            acc.y = fmaf(an, p0[i].y, acc.y);
            acc.z = fmaf(an, p0[i].z, acc.z);
            acc.w = fmaf(an, p0[i].w, acc.w);
        }
        // ---- Pass 2b: second half inline ----
        #pragma unroll
        for (int i = 8; i < 16; i++) {
            float4 x = __ldcs(reinterpret_cast<const float4*>(nbp + i*128 + 4*lane));
            float an = __shfl_sync(0xffffffffu, a, i + (lane & 16));
            acc.x = fmaf(an, x.x, acc.x);
            acc.y = fmaf(an, x.y, acc.y);
            acc.z = fmaf(an, x.z, acc.z);
            acc.w = fmaf(an, x.w, acc.w);
        }
        // Fold even/odd halves.
        acc.x += __shfl_xor_sync(0xffffffffu, acc.x, 16);
        acc.y += __shfl_xor_sync(0xffffffffu, acc.y, 16);
        acc.z += __shfl_xor_sync(0xffffffffu, acc.z, 16);
        acc.w += __shfl_xor_sync(0xffffffffu, acc.w, 16);

        const float4 sv = *reinterpret_cast<const float4*>(
            selfv + (size_t)pair*D_ + 4*q);
        float4 o = make_float4(sv.x + acc.x, sv.y + acc.y,
                               sv.z + acc.z, sv.w + acc.w);

        // ---- Linear: y[j] = b[j] + sum_d o[d]*W[j][d], j = 2*lane, 2*lane+1 ----
        float y0 = bb.x, y1 = bb.y;
        #pragma unroll
        for (int c = 0; c < 16; c++) {
            float ox = __shfl_sync(0xffffffffu, o.x, c);
            float oy = __shfl_sync(0xffffffffu, o.y, c);
            float oz = __shfl_sync(0xffffffffu, o.z, c);
            float ow = __shfl_sync(0xffffffffu, o.w, c);
            float4 wa = Wa[c][lane];
            float4 wb = Wb[c][lane];
            y0 = fmaf(ox, wa.x, fmaf(oy, wa.y, fmaf(oz, wa.z, fmaf(ow, wa.w, y0))));
            y1 = fmaf(ox, wb.x, fmaf(oy, wb.y, fmaf(oz, wb.z, fmaf(ow, wb.w, y1))));
        }

        float2 res = make_float2(fmaxf(y0, 0.f), fmaxf(y1, 0.f));
        __stcs(reinterpret_cast<float2*>(out + (size_t)pair*D_ + 2*lane), res);
    }
}

extern "C" void kernel_launch(void* const* d_in, const int* in_sizes, int n_in,
                              void* d_out, int out_size)
{
    const float* selfv = (const float*)d_in[0];  // self_vectors      [B,E,D]
    const float* nbv   = (const float*)d_in[1];  // neighbor_vectors  [B,E,N,D]
    const float* relv  = (const float*)d_in[2];  // neighbor_relations[B,E,N,D]
    const float* userv = (const float*)d_in[3];  // user_embeddings   [B,D]
    // d_in[4] = masks (unused)
    const float* W     = (const float*)d_in[5];  // [D,D]
    const float* bl    = (const float*)d_in[6];  // [D]
    float* out = (float*)d_out;

    int dev = 0, sms = 152, occ = 0;
    cudaGetDevice(&dev);
    cudaDeviceGetAttribute(&sms, cudaDevAttrMultiProcessorCount, dev);
    cudaOccupancyMaxActiveBlocksPerMultiprocessor(&occ, sum_aggregator_kernel, 256, 0);
    if (occ < 1) occ = 1;
    if (occ > 3) occ = 3;    // 24 warps/SM measured best (R5)
    int blocks = occ * sms;
    int max_blocks = BE_ / 8;
    if (blocks > max_blocks) blocks = max_blocks;
    int total_warps = blocks * 8;

    sum_aggregator_kernel<<<blocks, 256>>>(selfv, nbv, relv, userv, W, bl, out,
                                           total_warps);
}